// round 4
// baseline (speedup 1.0000x reference)
#include <cuda_runtime.h>
#include <cstdint>

#define NN 100000
#define NE 3200000
#define H  32

// __device__ scratch (no allocations allowed)
__device__ float g_W1f[2 * H];   // BN-folded W1
__device__ float g_b1f[H];       // BN-folded bias
__device__ float g_sums[NN * 3];
__device__ float g_counts[NN];

// ---------------------------------------------------------------------------
// Fold BN (eval mode) into the first linear layer:
//   h = (m@W1 - mean) * (gamma/sqrt(var+eps)) + beta
//     = m @ (W1 * s) + (beta - mean*s)
__global__ void prep_kernel(const float* __restrict__ W1,
                            const float* __restrict__ gamma,
                            const float* __restrict__ beta,
                            const float* __restrict__ mean,
                            const float* __restrict__ var) {
    int k = threadIdx.x;
    if (k < H) {
        float s = gamma[k] * rsqrtf(var[k] + 1e-5f);
        g_W1f[k]     = W1[k] * s;      // row 0 (norms)
        g_W1f[H + k] = W1[H + k] * s;  // row 1 (dots)
        g_b1f[k] = beta[k] - mean[k] * s;
    }
}

__global__ void zero_kernel() {
    int i = blockIdx.x * blockDim.x + threadIdx.x;
    if (i < NN * 3) g_sums[i] = 0.0f;
    if (i < NN)     g_counts[i] = 0.0f;
}

// ---------------------------------------------------------------------------
// Main per-edge kernel. One thread per edge.
__global__ void __launch_bounds__(256, 2) edge_kernel(
    const float* __restrict__ x,
    const int* __restrict__ ei,          // int32! jax x64-disabled downcasts int64
    const float* __restrict__ W2, const float* __restrict__ b2,
    const float* __restrict__ W3, const float* __restrict__ b3,
    const float* __restrict__ W4,
    const float* __restrict__ W5, const float* __restrict__ b5,
    float* __restrict__ out_m)
{
    __shared__ __align__(16) float sW2[H * H];
    __shared__ __align__(16) float sW3[H * H];
    __shared__ float sW1[2 * H], sb1[H], sb2[H], sb3[H], sW4[H], sW5[H];
    __shared__ float sb5;

    int tid = threadIdx.x;
    for (int t = tid; t < H * H; t += blockDim.x) { sW2[t] = W2[t]; sW3[t] = W3[t]; }
    if (tid < H) {
        sW1[tid]     = g_W1f[tid];
        sW1[H + tid] = g_W1f[H + tid];
        sb1[tid] = g_b1f[tid];
        sb2[tid] = b2[tid];
        sb3[tid] = b3[tid];
        sW4[tid] = W4[tid];
        sW5[tid] = W5[tid];
    }
    if (tid == 0) sb5 = b5[0];
    __syncthreads();

    long e = (long)blockIdx.x * blockDim.x + tid;
    if (e >= NE) return;

    int ni = ei[e];
    int nj = ei[(long)NE + e];
    // Defensive: never issue an out-of-range gather (turns a crash into a
    // diagnosable rel_err if the index layout assumption is wrong).
    if ((unsigned)ni >= NN || (unsigned)nj >= NN) return;

    float xi0 = __ldg(&x[3 * ni + 0]);
    float xi1 = __ldg(&x[3 * ni + 1]);
    float xi2 = __ldg(&x[3 * ni + 2]);
    float xj0 = __ldg(&x[3 * nj + 0]);
    float xj1 = __ldg(&x[3 * nj + 1]);
    float xj2 = __ldg(&x[3 * nj + 2]);

    float d0 = xi0 - xj0, d1 = xi1 - xj1, d2 = xi2 - xj2;
    float nsq = d0 * d0 + d1 * d1 + d2 * d2;
    float dot = xi0 * xj0 + xi1 * xj1 + xi2 * xj2;

    // psi(t) = sign(t) * log1p(|t|);  nsq >= 0
    float norms = log1pf(nsq);
    float dots  = copysignf(log1pf(fabsf(dot)), dot);

    // ---- layer 1 (BN folded) + ReLU ----
    float h1[H];
#pragma unroll
    for (int k = 0; k < H; k++) {
        float v = fmaf(norms, sW1[k], fmaf(dots, sW1[H + k], sb1[k]));
        h1[k] = fmaxf(v, 0.0f);
    }

    // ---- layer 2: h2 = ReLU(h1 @ W2 + b2) ----
    float h2[H];
#pragma unroll
    for (int k = 0; k < H; k++) h2[k] = sb2[k];
#pragma unroll 4
    for (int j = 0; j < H; j++) {
        float hj = h1[j];
        const float4* row = (const float4*)(sW2 + j * H);
#pragma unroll
        for (int k4 = 0; k4 < H / 4; k4++) {
            float4 w = row[k4];
            h2[4 * k4 + 0] = fmaf(hj, w.x, h2[4 * k4 + 0]);
            h2[4 * k4 + 1] = fmaf(hj, w.y, h2[4 * k4 + 1]);
            h2[4 * k4 + 2] = fmaf(hj, w.z, h2[4 * k4 + 2]);
            h2[4 * k4 + 3] = fmaf(hj, w.w, h2[4 * k4 + 3]);
        }
    }
#pragma unroll
    for (int k = 0; k < H; k++) h2[k] = fmaxf(h2[k], 0.0f);

    // ---- gate: w = sigmoid(h2 . W5 + b5) ----
    float z = sb5;
#pragma unroll
    for (int k = 0; k < H; k++) z = fmaf(h2[k], sW5[k], z);
    float wgt = 1.0f / (1.0f + expf(-z));

    // ---- m = h2 * w, write out ----
    float4* mo = (float4*)(out_m + (long)e * H);
#pragma unroll
    for (int k4 = 0; k4 < H / 4; k4++) {
        float4 v;
        v.x = h2[4 * k4 + 0] * wgt;
        v.y = h2[4 * k4 + 1] * wgt;
        v.z = h2[4 * k4 + 2] * wgt;
        v.w = h2[4 * k4 + 3] * wgt;
        mo[k4] = v;
    }

    // ---- phi_x: u = ReLU(m @ W3 + b3) = ReLU(w*(h2@W3) + b3); phix = u . W4 ----
    float a3[H];
#pragma unroll
    for (int k = 0; k < H; k++) a3[k] = 0.0f;
#pragma unroll 4
    for (int j = 0; j < H; j++) {
        float hj = h2[j];
        const float4* row = (const float4*)(sW3 + j * H);
#pragma unroll
        for (int k4 = 0; k4 < H / 4; k4++) {
            float4 w = row[k4];
            a3[4 * k4 + 0] = fmaf(hj, w.x, a3[4 * k4 + 0]);
            a3[4 * k4 + 1] = fmaf(hj, w.y, a3[4 * k4 + 1]);
            a3[4 * k4 + 2] = fmaf(hj, w.z, a3[4 * k4 + 2]);
            a3[4 * k4 + 3] = fmaf(hj, w.w, a3[4 * k4 + 3]);
        }
    }
    float phix = 0.0f;
#pragma unroll
    for (int k = 0; k < H; k++) {
        float u = fmaxf(fmaf(wgt, a3[k], sb3[k]), 0.0f);
        phix = fmaf(u, sW4[k], phix);
    }

    // ---- scatter-mean accumulation ----
    float u0 = fminf(fmaxf(d0 * phix, -100.0f), 100.0f);
    float u1 = fminf(fmaxf(d1 * phix, -100.0f), 100.0f);
    float u2 = fminf(fmaxf(d2 * phix, -100.0f), 100.0f);
    atomicAdd(&g_sums[3 * ni + 0], u0);
    atomicAdd(&g_sums[3 * ni + 1], u1);
    atomicAdd(&g_sums[3 * ni + 2], u2);
    atomicAdd(&g_counts[ni], 1.0f);
}

// ---------------------------------------------------------------------------
__global__ void node_kernel(const float* __restrict__ x, float* __restrict__ out_x) {
    int n = blockIdx.x * blockDim.x + threadIdx.x;
    if (n < NN) {
        float c = fmaxf(g_counts[n], 1.0f);
        float inv = 1.0f / c;
#pragma unroll
        for (int d = 0; d < 3; d++) {
            out_x[3 * n + d] = x[3 * n + d] + g_sums[3 * n + d] * inv;
        }
    }
}

// ---------------------------------------------------------------------------
extern "C" void kernel_launch(void* const* d_in, const int* in_sizes, int n_in,
                              void* d_out, int out_size) {
    const float* x   = (const float*)d_in[0];
    const int*   ei  = (const int*)d_in[1];     // int32 (jax default x64-disabled)
    const float* W1  = (const float*)d_in[2];
    const float* gma = (const float*)d_in[3];
    const float* bta = (const float*)d_in[4];
    const float* mea = (const float*)d_in[5];
    const float* var = (const float*)d_in[6];
    const float* W2  = (const float*)d_in[7];
    const float* b2  = (const float*)d_in[8];
    const float* W3  = (const float*)d_in[9];
    const float* b3  = (const float*)d_in[10];
    const float* W4  = (const float*)d_in[11];
    const float* W5  = (const float*)d_in[12];
    const float* b5  = (const float*)d_in[13];

    float* out_x = (float*)d_out;          // x_tilde: [NN, 3]
    float* out_m = out_x + (long)NN * 3;   // m: [NE, H]

    zero_kernel<<<(NN * 3 + 255) / 256, 256>>>();
    prep_kernel<<<1, 32>>>(W1, gma, bta, mea, var);
    edge_kernel<<<(NE + 255) / 256, 256>>>(x, ei, W2, b2, W3, b3, W4, W5, b5, out_m);
    node_kernel<<<(NN + 255) / 256, 256>>>(x, out_x);
}

// round 6
// speedup vs baseline: 1.3247x; 1.3247x over previous
#include <cuda_runtime.h>
#include <cstdint>

#define NN 100000
#define NE 3200000
#define H  32

typedef unsigned long long ull;

// __device__ scratch (no allocations allowed)
__device__ float g_W1f[2 * H];   // BN-folded W1
__device__ float g_b1f[H];       // BN-folded bias
__device__ float g_sums[NN * 3];
__device__ float g_counts[NN];

// ---- packed f32x2 helpers (sm_103a; ptxas will not auto-fuse these) ----
__device__ __forceinline__ ull ffma2(ull a, ull b, ull c) {
    ull d;
    asm("fma.rn.f32x2 %0, %1, %2, %3;" : "=l"(d) : "l"(a), "l"(b), "l"(c));
    return d;
}
__device__ __forceinline__ ull fmul2(ull a, ull b) {
    ull d;
    asm("mul.rn.f32x2 %0, %1, %2;" : "=l"(d) : "l"(a), "l"(b));
    return d;
}
__device__ __forceinline__ ull pack2(float lo, float hi) {
    ull r;
    asm("mov.b64 %0, {%1, %2};" : "=l"(r) : "f"(lo), "f"(hi));
    return r;
}
__device__ __forceinline__ float2 unpack2(ull v) {
    float2 f;
    asm("mov.b64 {%0, %1}, %2;" : "=f"(f.x), "=f"(f.y) : "l"(v));
    return f;
}

// ---------------------------------------------------------------------------
// Fold BN (eval mode) into the first linear layer.
__global__ void prep_kernel(const float* __restrict__ W1,
                            const float* __restrict__ gamma,
                            const float* __restrict__ beta,
                            const float* __restrict__ mean,
                            const float* __restrict__ var) {
    int k = threadIdx.x;
    if (k < H) {
        float s = gamma[k] * rsqrtf(var[k] + 1e-5f);
        g_W1f[k]     = W1[k] * s;      // row 0 (norms)
        g_W1f[H + k] = W1[H + k] * s;  // row 1 (dots)
        g_b1f[k] = beta[k] - mean[k] * s;
    }
}

__global__ void zero_kernel() {
    int i = blockIdx.x * blockDim.x + threadIdx.x;
    if (i < NN * 3) g_sums[i] = 0.0f;
    if (i < NN)     g_counts[i] = 0.0f;
}

// ---------------------------------------------------------------------------
// Main per-edge kernel. One thread per edge. Matmuls in packed f32x2.
__global__ void __launch_bounds__(256, 2) edge_kernel(
    const float* __restrict__ x,
    const int* __restrict__ ei,
    const float* __restrict__ W2, const float* __restrict__ b2,
    const float* __restrict__ W3, const float* __restrict__ b3,
    const float* __restrict__ W4,
    const float* __restrict__ W5, const float* __restrict__ b5,
    float* __restrict__ out_m)
{
    __shared__ __align__(16) float sW2[H * H];
    __shared__ __align__(16) float sW3[H * H];
    __shared__ __align__(16) float sW1[2 * H];
    __shared__ __align__(16) float sb1[H], sb2[H], sb3[H], sW4[H], sW5[H];
    __shared__ float sb5;

    int tid = threadIdx.x;
    for (int t = tid; t < H * H; t += blockDim.x) { sW2[t] = W2[t]; sW3[t] = W3[t]; }
    if (tid < H) {
        sW1[tid]     = g_W1f[tid];
        sW1[H + tid] = g_W1f[H + tid];
        sb1[tid] = g_b1f[tid];
        sb2[tid] = b2[tid];
        sb3[tid] = b3[tid];
        sW4[tid] = W4[tid];
        sW5[tid] = W5[tid];
    }
    if (tid == 0) sb5 = b5[0];
    __syncthreads();

    long e = (long)blockIdx.x * blockDim.x + tid;
    if (e >= NE) return;

    int ni = ei[e];
    int nj = ei[(long)NE + e];
    if ((unsigned)ni >= NN || (unsigned)nj >= NN) return;

    float xi0 = __ldg(&x[3 * ni + 0]);
    float xi1 = __ldg(&x[3 * ni + 1]);
    float xi2 = __ldg(&x[3 * ni + 2]);
    float xj0 = __ldg(&x[3 * nj + 0]);
    float xj1 = __ldg(&x[3 * nj + 1]);
    float xj2 = __ldg(&x[3 * nj + 2]);

    float d0 = xi0 - xj0, d1 = xi1 - xj1, d2 = xi2 - xj2;
    float nsq = d0 * d0 + d1 * d1 + d2 * d2;
    float dot = xi0 * xj0 + xi1 * xj1 + xi2 * xj2;

    // psi(t) = sign(t) * log1p(|t|); nsq >= 0
    float norms = log1pf(nsq);
    float dots  = copysignf(log1pf(fabsf(dot)), dot);

    // ---- layer 1 (BN folded) + ReLU, packed ----
    float h1[H];
    {
        ull n2 = pack2(norms, norms);
        ull t2 = pack2(dots, dots);
        const ull* w1r0 = (const ull*)(sW1);
        const ull* w1r1 = (const ull*)(sW1 + H);
        const ull* b1p  = (const ull*)(sb1);
#pragma unroll
        for (int k2 = 0; k2 < H / 2; k2++) {
            ull v = ffma2(n2, w1r0[k2], ffma2(t2, w1r1[k2], b1p[k2]));
            float2 f = unpack2(v);
            h1[2 * k2 + 0] = fmaxf(f.x, 0.0f);
            h1[2 * k2 + 1] = fmaxf(f.y, 0.0f);
        }
    }

    // ---- layer 2: h2 = ReLU(h1 @ W2 + b2), packed accumulators ----
    ull acc[H / 2];
    {
        const ull* b2p = (const ull*)(sb2);
#pragma unroll
        for (int k2 = 0; k2 < H / 2; k2++) acc[k2] = b2p[k2];
    }
#pragma unroll 4
    for (int j = 0; j < H; j++) {
        ull hjj = pack2(h1[j], h1[j]);
        const ulonglong2* row = (const ulonglong2*)(sW2 + j * H);
#pragma unroll
        for (int q = 0; q < H / 4; q++) {
            ulonglong2 w = row[q];
            acc[2 * q + 0] = ffma2(hjj, w.x, acc[2 * q + 0]);
            acc[2 * q + 1] = ffma2(hjj, w.y, acc[2 * q + 1]);
        }
    }
    float h2[H];
#pragma unroll
    for (int k2 = 0; k2 < H / 2; k2++) {
        float2 f = unpack2(acc[k2]);
        h2[2 * k2 + 0] = fmaxf(f.x, 0.0f);
        h2[2 * k2 + 1] = fmaxf(f.y, 0.0f);
    }

    // ---- gate: w = sigmoid(h2 . W5 + b5) ----
    float z = sb5;
#pragma unroll
    for (int k = 0; k < H; k++) z = fmaf(h2[k], sW5[k], z);
    float wgt = 1.0f / (1.0f + expf(-z));

    // ---- m = h2 * wgt, write out (packed mul) ----
    {
        ull w2p = pack2(wgt, wgt);
        ull mv[H / 2];
#pragma unroll
        for (int k2 = 0; k2 < H / 2; k2++)
            mv[k2] = fmul2(pack2(h2[2 * k2], h2[2 * k2 + 1]), w2p);
        ulonglong2* mo = (ulonglong2*)(out_m + (long)e * H);
#pragma unroll
        for (int q = 0; q < H / 4; q++) {
            ulonglong2 v;
            v.x = mv[2 * q + 0];
            v.y = mv[2 * q + 1];
            mo[q] = v;
        }
    }

    // ---- phi_x: a3 = h2 @ W3 (packed); u = ReLU(wgt*a3 + b3); phix = u.W4 ----
#pragma unroll
    for (int k2 = 0; k2 < H / 2; k2++) acc[k2] = 0ULL;  // reuse acc
#pragma unroll 4
    for (int j = 0; j < H; j++) {
        ull hjj = pack2(h2[j], h2[j]);
        const ulonglong2* row = (const ulonglong2*)(sW3 + j * H);
#pragma unroll
        for (int q = 0; q < H / 4; q++) {
            ulonglong2 w = row[q];
            acc[2 * q + 0] = ffma2(hjj, w.x, acc[2 * q + 0]);
            acc[2 * q + 1] = ffma2(hjj, w.y, acc[2 * q + 1]);
        }
    }
    float phix = 0.0f;
    {
        ull w2p = pack2(wgt, wgt);
        const ull* b3p = (const ull*)(sb3);
#pragma unroll
        for (int k2 = 0; k2 < H / 2; k2++) {
            float2 u = unpack2(ffma2(w2p, acc[k2], b3p[k2]));
            float u0 = fmaxf(u.x, 0.0f);
            float u1 = fmaxf(u.y, 0.0f);
            phix = fmaf(u0, sW4[2 * k2 + 0], phix);
            phix = fmaf(u1, sW4[2 * k2 + 1], phix);
        }
    }

    // ---- scatter-mean accumulation ----
    float u0 = fminf(fmaxf(d0 * phix, -100.0f), 100.0f);
    float u1 = fminf(fmaxf(d1 * phix, -100.0f), 100.0f);
    float u2 = fminf(fmaxf(d2 * phix, -100.0f), 100.0f);
    atomicAdd(&g_sums[3 * ni + 0], u0);
    atomicAdd(&g_sums[3 * ni + 1], u1);
    atomicAdd(&g_sums[3 * ni + 2], u2);
    atomicAdd(&g_counts[ni], 1.0f);
}

// ---------------------------------------------------------------------------
__global__ void node_kernel(const float* __restrict__ x, float* __restrict__ out_x) {
    int n = blockIdx.x * blockDim.x + threadIdx.x;
    if (n < NN) {
        float c = fmaxf(g_counts[n], 1.0f);
        float inv = 1.0f / c;
#pragma unroll
        for (int d = 0; d < 3; d++) {
            out_x[3 * n + d] = x[3 * n + d] + g_sums[3 * n + d] * inv;
        }
    }
}

// ---------------------------------------------------------------------------
extern "C" void kernel_launch(void* const* d_in, const int* in_sizes, int n_in,
                              void* d_out, int out_size) {
    const float* x   = (const float*)d_in[0];
    const int*   ei  = (const int*)d_in[1];     // int32 (jax default x64-disabled)
    const float* W1  = (const float*)d_in[2];
    const float* gma = (const float*)d_in[3];
    const float* bta = (const float*)d_in[4];
    const float* mea = (const float*)d_in[5];
    const float* var = (const float*)d_in[6];
    const float* W2  = (const float*)d_in[7];
    const float* b2  = (const float*)d_in[8];
    const float* W3  = (const float*)d_in[9];
    const float* b3  = (const float*)d_in[10];
    const float* W4  = (const float*)d_in[11];
    const float* W5  = (const float*)d_in[12];
    const float* b5  = (const float*)d_in[13];

    float* out_x = (float*)d_out;          // x_tilde: [NN, 3]
    float* out_m = out_x + (long)NN * 3;   // m: [NE, H]

    zero_kernel<<<(NN * 3 + 255) / 256, 256>>>();
    prep_kernel<<<1, 32>>>(W1, gma, bta, mea, var);
    edge_kernel<<<(NE + 255) / 256, 256>>>(x, ei, W2, b2, W3, b3, W4, W5, b5, out_m);
    node_kernel<<<(NN + 255) / 256, 256>>>(x, out_x);
}

// round 8
// speedup vs baseline: 1.8453x; 1.3930x over previous
#include <cuda_runtime.h>
#include <cstdint>

#define NN 100000
#define NE 3200000
#define H  32

typedef unsigned long long ull;

// __device__ scratch (no allocations allowed)
__device__ float4 g_L1q[H];      // per-channel (A,B,C,0): h1 = relu(A*norms + B*dots + C)
__device__ float g_sums[NN * 3];
__device__ float g_counts[NN];

// ---- packed f32x2 helpers (sm_103a; ptxas will not auto-fuse these) ----
__device__ __forceinline__ ull ffma2(ull a, ull b, ull c) {
    ull d;
    asm("fma.rn.f32x2 %0, %1, %2, %3;" : "=l"(d) : "l"(a), "l"(b), "l"(c));
    return d;
}
__device__ __forceinline__ ull fmul2(ull a, ull b) {
    ull d;
    asm("mul.rn.f32x2 %0, %1, %2;" : "=l"(d) : "l"(a), "l"(b));
    return d;
}
__device__ __forceinline__ ull fadd2(ull a, ull b) {
    ull d;
    asm("add.rn.f32x2 %0, %1, %2;" : "=l"(d) : "l"(a), "l"(b));
    return d;
}
__device__ __forceinline__ ull pack2(float lo, float hi) {
    ull r;
    asm("mov.b64 %0, {%1, %2};" : "=l"(r) : "f"(lo), "f"(hi));
    return r;
}
__device__ __forceinline__ float2 unpack2(ull v) {
    float2 f;
    asm("mov.b64 {%0, %1}, %2;" : "=f"(f.x), "=f"(f.y) : "l"(v));
    return f;
}

// ---------------------------------------------------------------------------
// Fold BN (eval mode) into the first linear layer; build the per-channel LUT.
__global__ void prep_kernel(const float* __restrict__ W1,
                            const float* __restrict__ gamma,
                            const float* __restrict__ beta,
                            const float* __restrict__ mean,
                            const float* __restrict__ var) {
    int k = threadIdx.x;
    if (k < H) {
        float s = gamma[k] * rsqrtf(var[k] + 1e-5f);
        g_L1q[k] = make_float4(W1[k] * s,            // A (norms coeff)
                               W1[H + k] * s,        // B (dots coeff)
                               beta[k] - mean[k] * s, // C (folded bias)
                               0.0f);
    }
}

__global__ void zero_kernel() {
    int i = blockIdx.x * blockDim.x + threadIdx.x;
    if (i < NN * 3) g_sums[i] = 0.0f;
    if (i < NN)     g_counts[i] = 0.0f;
}

// ---------------------------------------------------------------------------
// Main edge kernel. TWO edges per thread: each shared weight row is loaded
// once and consumed by both edges (halves LDS traffic vs 1 edge/thread).
__global__ void __launch_bounds__(256, 2) edge_kernel(
    const float* __restrict__ x,
    const int* __restrict__ ei,
    const float* __restrict__ W2, const float* __restrict__ b2,
    const float* __restrict__ W3, const float* __restrict__ b3,
    const float* __restrict__ W4,
    const float* __restrict__ W5, const float* __restrict__ b5,
    float* __restrict__ out_m)
{
    __shared__ __align__(16) float sW2[H * H];    // row-major [j][k]
    __shared__ __align__(16) float sW3T[H * H];   // TRANSPOSED: [k][j]
    __shared__ __align__(16) float4 sL1[H];
    __shared__ __align__(16) float sb2[H], sb3[H], sW4[H], sW5[H];
    __shared__ float sb5v;

    int tid = threadIdx.x;
    for (int t = tid; t < H * H; t += 256) {
        sW2[t] = W2[t];
        int k = t >> 5, j = t & 31;
        sW3T[t] = W3[j * H + k];   // strided global read, L2-hit; conflict-free smem write
    }
    if (tid < H) {
        sL1[tid] = g_L1q[tid];
        sb2[tid] = b2[tid];
        sb3[tid] = b3[tid];
        sW4[tid] = W4[tid];
        sW5[tid] = W5[tid];
    }
    if (tid == 0) sb5v = b5[0];
    __syncthreads();

    long e0 = ((long)blockIdx.x * 256 + tid) * 2;   // grid sized so e0+1 < NE always
    long e1 = e0 + 1;

    int2 di = *(const int2*)(ei + e0);              // dest nodes (row i)
    int2 sj = *(const int2*)(ei + (long)NE + e0);   // src nodes (row j)
    int ia = di.x, ib = di.y, ja = sj.x, jb = sj.y;
    if ((unsigned)ia >= NN || (unsigned)ib >= NN ||
        (unsigned)ja >= NN || (unsigned)jb >= NN) return;

    float xa0 = __ldg(&x[3 * ia + 0]), xa1 = __ldg(&x[3 * ia + 1]), xa2 = __ldg(&x[3 * ia + 2]);
    float ya0 = __ldg(&x[3 * ja + 0]), ya1 = __ldg(&x[3 * ja + 1]), ya2 = __ldg(&x[3 * ja + 2]);
    float xb0 = __ldg(&x[3 * ib + 0]), xb1 = __ldg(&x[3 * ib + 1]), xb2 = __ldg(&x[3 * ib + 2]);
    float yb0 = __ldg(&x[3 * jb + 0]), yb1 = __ldg(&x[3 * jb + 1]), yb2 = __ldg(&x[3 * jb + 2]);

    float da0 = xa0 - ya0, da1 = xa1 - ya1, da2 = xa2 - ya2;
    float db0 = xb0 - yb0, db1 = xb1 - yb1, db2 = xb2 - yb2;
    float nsq_a = da0 * da0 + da1 * da1 + da2 * da2;
    float nsq_b = db0 * db0 + db1 * db1 + db2 * db2;
    float dot_a = xa0 * ya0 + xa1 * ya1 + xa2 * ya2;
    float dot_b = xb0 * yb0 + xb1 * yb1 + xb2 * yb2;

    float na = log1pf(nsq_a);
    float nb = log1pf(nsq_b);
    float ta = copysignf(log1pf(fabsf(dot_a)), dot_a);
    float tb = copysignf(log1pf(fabsf(dot_b)), dot_b);

    // ---- fused layer1 + layer2: acc = b2 + sum_j relu(l1_j) * W2[j,:] ----
    ull acc_a[H / 2], acc_b[H / 2];
    {
        const ull* b2p = (const ull*)sb2;
#pragma unroll
        for (int q = 0; q < H / 2; q++) { acc_a[q] = b2p[q]; acc_b[q] = b2p[q]; }
    }
#pragma unroll 2
    for (int j = 0; j < H; j++) {
        float4 c = sL1[j];
        float ha = fmaxf(fmaf(na, c.x, fmaf(ta, c.y, c.z)), 0.0f);
        float hb = fmaxf(fmaf(nb, c.x, fmaf(tb, c.y, c.z)), 0.0f);
        ull hap = pack2(ha, ha);
        ull hbp = pack2(hb, hb);
        const ulonglong2* row = (const ulonglong2*)(sW2 + j * H);
#pragma unroll
        for (int q = 0; q < H / 4; q++) {
            ulonglong2 w = row[q];                 // one load, two edges
            acc_a[2 * q + 0] = ffma2(hap, w.x, acc_a[2 * q + 0]);
            acc_a[2 * q + 1] = ffma2(hap, w.y, acc_a[2 * q + 1]);
            acc_b[2 * q + 0] = ffma2(hbp, w.x, acc_b[2 * q + 0]);
            acc_b[2 * q + 1] = ffma2(hbp, w.y, acc_b[2 * q + 1]);
        }
    }

    // ---- h2 = relu(acc), kept packed (channel pairs) ----
    ull h2a[H / 2], h2b[H / 2];
#pragma unroll
    for (int q = 0; q < H / 2; q++) {
        float2 fa = unpack2(acc_a[q]);
        float2 fb = unpack2(acc_b[q]);
        h2a[q] = pack2(fmaxf(fa.x, 0.0f), fmaxf(fa.y, 0.0f));
        h2b[q] = pack2(fmaxf(fb.x, 0.0f), fmaxf(fb.y, 0.0f));
    }

    // ---- gate: wgt = sigmoid(h2 . W5 + b5) ----
    float wgt_a, wgt_b;
    {
        const ull* w5p = (const ull*)sW5;
        ull za0 = 0, za1 = 0, zb0 = 0, zb1 = 0;
#pragma unroll
        for (int q = 0; q < H / 2; q += 2) {
            za0 = ffma2(h2a[q], w5p[q], za0);
            za1 = ffma2(h2a[q + 1], w5p[q + 1], za1);
            zb0 = ffma2(h2b[q], w5p[q], zb0);
            zb1 = ffma2(h2b[q + 1], w5p[q + 1], zb1);
        }
        float2 fa = unpack2(fadd2(za0, za1));
        float2 fb = unpack2(fadd2(zb0, zb1));
        float za = fa.x + fa.y + sb5v;
        float zb = fb.x + fb.y + sb5v;
        wgt_a = 1.0f / (1.0f + expf(-za));
        wgt_b = 1.0f / (1.0f + expf(-zb));
    }

    // ---- m = h2 * wgt, write out ----
    {
        ull wpa = pack2(wgt_a, wgt_a);
        ull wpb = pack2(wgt_b, wgt_b);
        ulonglong2* moa = (ulonglong2*)(out_m + e0 * H);
        ulonglong2* mob = (ulonglong2*)(out_m + e1 * H);
#pragma unroll
        for (int q = 0; q < H / 4; q++) {
            ulonglong2 va, vb;
            va.x = fmul2(h2a[2 * q + 0], wpa);
            va.y = fmul2(h2a[2 * q + 1], wpa);
            vb.x = fmul2(h2b[2 * q + 0], wpb);
            vb.y = fmul2(h2b[2 * q + 1], wpb);
            moa[q] = va;
            mob[q] = vb;
        }
    }

    // ---- phi_x, k-outer vs transposed W3: a3_k = h2 . W3T[k]; shared rows
    //      serve both edges. u = relu(wgt*a3 + b3); phix = u . W4 ----
    float phix_a0 = 0.0f, phix_a1 = 0.0f, phix_b0 = 0.0f, phix_b1 = 0.0f;
#pragma unroll 2
    for (int k = 0; k < H; k++) {
        const ulonglong2* row = (const ulonglong2*)(sW3T + k * H);
        ull sa0 = 0, sa1 = 0, sb0 = 0, sb1 = 0;
#pragma unroll
        for (int q = 0; q < H / 4; q++) {
            ulonglong2 w = row[q];                 // one load, two edges
            sa0 = ffma2(h2a[2 * q + 0], w.x, sa0);
            sa1 = ffma2(h2a[2 * q + 1], w.y, sa1);
            sb0 = ffma2(h2b[2 * q + 0], w.x, sb0);
            sb1 = ffma2(h2b[2 * q + 1], w.y, sb1);
        }
        float2 fa = unpack2(fadd2(sa0, sa1));
        float2 fb = unpack2(fadd2(sb0, sb1));
        float a3a = fa.x + fa.y;
        float a3b = fb.x + fb.y;
        float b3k = sb3[k], w4k = sW4[k];
        float ua = fmaxf(fmaf(wgt_a, a3a, b3k), 0.0f);
        float ub = fmaxf(fmaf(wgt_b, a3b, b3k), 0.0f);
        if (k & 1) { phix_a1 = fmaf(ua, w4k, phix_a1); phix_b1 = fmaf(ub, w4k, phix_b1); }
        else       { phix_a0 = fmaf(ua, w4k, phix_a0); phix_b0 = fmaf(ub, w4k, phix_b0); }
    }
    float phix_a = phix_a0 + phix_a1;
    float phix_b = phix_b0 + phix_b1;

    // ---- scatter-mean accumulation ----
    float ua0 = fminf(fmaxf(da0 * phix_a, -100.0f), 100.0f);
    float ua1 = fminf(fmaxf(da1 * phix_a, -100.0f), 100.0f);
    float ua2 = fminf(fmaxf(da2 * phix_a, -100.0f), 100.0f);
    float ub0 = fminf(fmaxf(db0 * phix_b, -100.0f), 100.0f);
    float ub1 = fminf(fmaxf(db1 * phix_b, -100.0f), 100.0f);
    float ub2 = fminf(fmaxf(db2 * phix_b, -100.0f), 100.0f);
    atomicAdd(&g_sums[3 * ia + 0], ua0);
    atomicAdd(&g_sums[3 * ia + 1], ua1);
    atomicAdd(&g_sums[3 * ia + 2], ua2);
    atomicAdd(&g_counts[ia], 1.0f);
    atomicAdd(&g_sums[3 * ib + 0], ub0);
    atomicAdd(&g_sums[3 * ib + 1], ub1);
    atomicAdd(&g_sums[3 * ib + 2], ub2);
    atomicAdd(&g_counts[ib], 1.0f);
}

// ---------------------------------------------------------------------------
__global__ void node_kernel(const float* __restrict__ x, float* __restrict__ out_x) {
    int n = blockIdx.x * blockDim.x + threadIdx.x;
    if (n < NN) {
        float c = fmaxf(g_counts[n], 1.0f);
        float inv = 1.0f / c;
#pragma unroll
        for (int d = 0; d < 3; d++) {
            out_x[3 * n + d] = x[3 * n + d] + g_sums[3 * n + d] * inv;
        }
    }
}

// ---------------------------------------------------------------------------
extern "C" void kernel_launch(void* const* d_in, const int* in_sizes, int n_in,
                              void* d_out, int out_size) {
    const float* x   = (const float*)d_in[0];
    const int*   ei  = (const int*)d_in[1];     // int32 (jax default x64-disabled)
    const float* W1  = (const float*)d_in[2];
    const float* gma = (const float*)d_in[3];
    const float* bta = (const float*)d_in[4];
    const float* mea = (const float*)d_in[5];
    const float* var = (const float*)d_in[6];
    const float* W2  = (const float*)d_in[7];
    const float* b2  = (const float*)d_in[8];
    const float* W3  = (const float*)d_in[9];
    const float* b3  = (const float*)d_in[10];
    const float* W4  = (const float*)d_in[11];
    const float* W5  = (const float*)d_in[12];
    const float* b5  = (const float*)d_in[13];

    float* out_x = (float*)d_out;          // x_tilde: [NN, 3]
    float* out_m = out_x + (long)NN * 3;   // m: [NE, H]

    zero_kernel<<<(NN * 3 + 255) / 256, 256>>>();
    prep_kernel<<<1, 32>>>(W1, gma, bta, mea, var);
    edge_kernel<<<NE / 512, 256>>>(x, ei, W2, b2, W3, b3, W4, W5, b5, out_m);  // 2 edges/thread
    node_kernel<<<(NN + 255) / 256, 256>>>(x, out_x);
}